// round 4
// baseline (speedup 1.0000x reference)
#include <cuda_runtime.h>

#define NN      8000
#define NFEATD  512
#define NHID    128
#define NCLS    64
#define CAP     128   // max edges per row (Binomial(8000,0.002): mean 16, P(>64) ~ 0)

// ---- persistent scratch (no allocs allowed) ----
__device__ float g_h[NN * NHID];        // h = relu(xW0+b0) (== h0)
__device__ float g_li0[NN * NHID];
__device__ float g_li1[NN * NHID];
__device__ float g_pseudo[NN * NCLS];
__device__ float g_yhat[NN * NCLS];
__device__ int   g_cols[NN * CAP];
__device__ int   g_nnz[NN];

// ============================================================
// h = relu(x @ W0 + b0); also li0 = h
// x:[8000,512] W0:[512,128]  BM=64 BN=128 BK=16, 256 thr, 4x8 micro
// ============================================================
__global__ void k_h_gemm(const float* __restrict__ A, const float* __restrict__ W,
                         const float* __restrict__ bias) {
    __shared__ float As[16][65];
    __shared__ float Bs[16][128];
    const int br  = blockIdx.x * 64;
    const int tid = threadIdx.x;
    const int tx  = tid & 15;   // col group
    const int ty  = tid >> 4;   // row group
    float acc[4][8];
#pragma unroll
    for (int i = 0; i < 4; i++)
#pragma unroll
        for (int j = 0; j < 8; j++) acc[i][j] = 0.f;

    for (int k0 = 0; k0 < NFEATD; k0 += 16) {
#pragma unroll
        for (int l = 0; l < 4; l++) {
            int e = tid + l * 256;
            int r = e >> 4, kk = e & 15;
            As[kk][r] = A[(size_t)(br + r) * NFEATD + k0 + kk];
        }
#pragma unroll
        for (int l = 0; l < 8; l++) {
            int e = tid + l * 256;
            int kk = e >> 7, c = e & 127;
            Bs[kk][c] = W[(size_t)(k0 + kk) * NHID + c];
        }
        __syncthreads();
#pragma unroll
        for (int kk = 0; kk < 16; kk++) {
            float ra[4], rb[8];
#pragma unroll
            for (int i = 0; i < 4; i++) ra[i] = As[kk][ty * 4 + i];
#pragma unroll
            for (int j = 0; j < 8; j++) rb[j] = Bs[kk][tx * 8 + j];
#pragma unroll
            for (int i = 0; i < 4; i++)
#pragma unroll
                for (int j = 0; j < 8; j++) acc[i][j] += ra[i] * rb[j];
        }
        __syncthreads();
    }
#pragma unroll
    for (int i = 0; i < 4; i++) {
        int r = br + ty * 4 + i;
#pragma unroll
        for (int j = 0; j < 8; j++) {
            int c = tx * 8 + j;
            float v = fmaxf(acc[i][j] + bias[c], 0.f);
            g_h[(size_t)r * NHID + c]   = v;
            g_li0[(size_t)r * NHID + c] = v;
        }
    }
}

// ============================================================
// Pseudo = h @ W1 + b1   (one block of 64 threads per row)
// ============================================================
__global__ void k_pseudo(const float* __restrict__ W1, const float* __restrict__ b1) {
    const int i = blockIdx.x, t = threadIdx.x;
    __shared__ float sh[NHID];
    sh[t]      = g_h[(size_t)i * NHID + t];
    sh[t + 64] = g_h[(size_t)i * NHID + t + 64];
    __syncthreads();
    float acc = b1[t];
#pragma unroll 8
    for (int k = 0; k < NHID; k++) acc += sh[k] * W1[k * NCLS + t];
    g_pseudo[(size_t)i * NCLS + t] = acc;
}

// ============================================================
// Pseudo[idx_train] += 0.1 * y_label[idx_train]  (dup-safe atomics)
// ============================================================
__global__ void k_inject(const int* __restrict__ idx, const float* __restrict__ y) {
    const int t = blockIdx.x;     // 500 train indices
    const int c = threadIdx.x;    // 64 classes
    const int r = idx[t];
    float v = 0.1f * y[(size_t)r * NCLS + c];
    if (v != 0.f) atomicAdd(&g_pseudo[(size_t)r * NCLS + c], v);
}

// ============================================================
// yhat = softmax(Pseudo); also copies (post-injection) Pseudo to output
// ============================================================
__global__ void k_softmax(float* __restrict__ out_pseudo) {
    const int i = blockIdx.x, t = threadIdx.x;   // 64 threads
    __shared__ float red[NCLS];
    float v = g_pseudo[(size_t)i * NCLS + t];
    out_pseudo[(size_t)i * NCLS + t] = v;
    red[t] = v; __syncthreads();
#pragma unroll
    for (int o = 32; o; o >>= 1) { if (t < o) red[t] = fmaxf(red[t], red[t + o]); __syncthreads(); }
    float mx = red[0]; __syncthreads();
    float e = expf(v - mx);
    red[t] = e; __syncthreads();
#pragma unroll
    for (int o = 32; o; o >>= 1) { if (t < o) red[t] += red[t + o]; __syncthreads(); }
    g_yhat[(size_t)i * NCLS + t] = e / red[0];
}

// ============================================================
// CSR structure of binary adj (values are all 1.0 -> store cols only)
// One block (256 thr) per row, float4 scan of 8000 cols.
// ============================================================
__global__ void k_csr(const float* __restrict__ adj) {
    const int i = blockIdx.x, t = threadIdx.x;
    __shared__ int cnt;
    if (t == 0) cnt = 0;
    __syncthreads();
    const float4* row4 = (const float4*)(adj + (size_t)i * NN);
    for (int j = t; j < NN / 4; j += 256) {
        float4 v = row4[j];
        if (v.x != 0.f) { int p = atomicAdd(&cnt, 1); if (p < CAP) g_cols[i * CAP + p] = 4 * j + 0; }
        if (v.y != 0.f) { int p = atomicAdd(&cnt, 1); if (p < CAP) g_cols[i * CAP + p] = 4 * j + 1; }
        if (v.z != 0.f) { int p = atomicAdd(&cnt, 1); if (p < CAP) g_cols[i * CAP + p] = 4 * j + 2; }
        if (v.w != 0.f) { int p = atomicAdd(&cnt, 1); if (p < CAP) g_cols[i * CAP + p] = 4 * j + 3; }
    }
    __syncthreads();
    if (t == 0) g_nnz[i] = cnt < CAP ? cnt : CAP;
}

// ============================================================
// One propagation layer, fused:
//   m_e = dot(yhat_i, yhat_j)  (edge weights; adj value is 1)
//   scale = 0.9 / max(sum_e m_e, eps)
//   li_out[i,:] = L2norm( sum_e (m_e*scale)*li_in[j,:] + 0.1*h0[i,:] )
// One block (128 thr) per row.
// ============================================================
__global__ void k_layer(int phase) {
    const int i = blockIdx.x, t = threadIdx.x;
    const float* li_in  = phase ? g_li1 : g_li0;
    float*       li_out = phase ? g_li0 : g_li1;

    __shared__ float syh[NCLS];
    __shared__ int   sj[CAP];
    __shared__ float sw[CAP];
    __shared__ float red[NHID];
    __shared__ float sscale;

    const int nnz = g_nnz[i];
    if (t < NCLS) syh[t] = g_yhat[(size_t)i * NCLS + t];
    for (int e = t; e < nnz; e += 128) sj[e] = g_cols[i * CAP + e];
    __syncthreads();

    const int warp = t >> 5, lane = t & 31;
    for (int e = warp; e < nnz; e += 4) {
        const float* yj = &g_yhat[(size_t)sj[e] * NCLS];
        float p = syh[2 * lane] * yj[2 * lane] + syh[2 * lane + 1] * yj[2 * lane + 1];
#pragma unroll
        for (int o = 16; o; o >>= 1) p += __shfl_down_sync(0xffffffffu, p, o);
        if (lane == 0) sw[e] = p;
    }
    __syncthreads();
    if (t == 0) {
        float s = 0.f;
        for (int e = 0; e < nnz; e++) s += sw[e];
        sscale = 0.9f / fmaxf(s, 1e-12f);
    }
    __syncthreads();
    const float scale = sscale;

    float acc = 0.1f * g_h[(size_t)i * NHID + t];
    for (int e = 0; e < nnz; e++)
        acc += (sw[e] * scale) * li_in[(size_t)sj[e] * NHID + t];

    red[t] = acc * acc; __syncthreads();
#pragma unroll
    for (int o = 64; o; o >>= 1) { if (t < o) red[t] += red[t + o]; __syncthreads(); }
    float inv = 1.f / fmaxf(sqrtf(red[0]), 1e-12f);
    li_out[(size_t)i * NHID + t] = acc * inv;
}

// ============================================================
// out = log_softmax(li @ W2 + b2)   (li lives in g_li0 after 2 layers)
// ============================================================
__global__ void k_out(const float* __restrict__ W2, const float* __restrict__ b2,
                      float* __restrict__ out) {
    const int i = blockIdx.x, t = threadIdx.x;   // 64 threads
    __shared__ float sli[NHID];
    __shared__ float red[NCLS];
    sli[t]      = g_li0[(size_t)i * NHID + t];
    sli[t + 64] = g_li0[(size_t)i * NHID + t + 64];
    __syncthreads();
    float v = b2[t];
#pragma unroll 8
    for (int k = 0; k < NHID; k++) v += sli[k] * W2[k * NCLS + t];
    red[t] = v; __syncthreads();
#pragma unroll
    for (int o = 32; o; o >>= 1) { if (t < o) red[t] = fmaxf(red[t], red[t + o]); __syncthreads(); }
    float mx = red[0]; __syncthreads();
    red[t] = expf(v - mx); __syncthreads();
#pragma unroll
    for (int o = 32; o; o >>= 1) { if (t < o) red[t] += red[t + o]; __syncthreads(); }
    out[(size_t)i * NCLS + t] = v - mx - logf(red[0]);
}

// ============================================================
extern "C" void kernel_launch(void* const* d_in, const int* in_sizes, int n_in,
                              void* d_out, int out_size) {
    const float* x   = (const float*)d_in[0];
    const float* adj = (const float*)d_in[1];
    const float* y   = (const float*)d_in[2];
    const int*   idx = (const int*)  d_in[3];
    const float* W0  = (const float*)d_in[4];
    const float* b0  = (const float*)d_in[5];
    const float* W1  = (const float*)d_in[6];
    const float* b1  = (const float*)d_in[7];
    const float* W2  = (const float*)d_in[8];
    const float* b2  = (const float*)d_in[9];
    (void)in_sizes; (void)n_in; (void)out_size;

    float* out_logsm  = (float*)d_out;                         // [8000,64]
    float* out_pseudo = (float*)d_out + (size_t)NN * NCLS;     // [8000,64]

    k_csr<<<NN, 256>>>(adj);                  // structure of adj (256 MB scan)
    k_h_gemm<<<NN / 64, 256>>>(x, W0, b0);    // h, li0
    k_pseudo<<<NN, 64>>>(W1, b1);
    k_inject<<<500, 64>>>(idx, y);
    k_softmax<<<NN, 64>>>(out_pseudo);        // yhat + Pseudo output
    k_layer<<<NN, 128>>>(0);                  // li0 -> li1
    k_layer<<<NN, 128>>>(1);                  // li1 -> li0
    k_out<<<NN, 64>>>(W2, b2, out_logsm);     // log_softmax output
}

// round 7
// speedup vs baseline: 1.0421x; 1.0421x over previous
#include <cuda_runtime.h>

#define NN      8000
#define NFEATD  512
#define NHID    128
#define NCLS    64
#define CAP     128

// ---- persistent scratch (no allocs allowed) ----
__device__ float g_h[NN * NHID];        // h = relu(xW0+b0) (== h0)
__device__ float g_li0[NN * NHID];
__device__ float g_li1[NN * NHID];
__device__ float g_yhat[NN * NCLS];
__device__ int   g_cols[NN * CAP];
__device__ int   g_nnz[NN];

// ============================================================
// Merged kernel: blocks [0,125) do the h-GEMM tiles,
// blocks [125, 8125) extract CSR structure of one adj row each.
// Memory-bound CSR blocks backfill SMs idle during the 125-block GEMM.
// ============================================================
#define SM_AS   (2 * 16 * 65)     // double-buffered As[2][16][65]
#define SM_BS   (2 * 16 * 128)    // double-buffered Bs[2][16][128]

__global__ void __launch_bounds__(256) k_main(
        const float* __restrict__ x,  const float* __restrict__ W0,
        const float* __restrict__ b0, const float* __restrict__ adj) {
    __shared__ __align__(16) float smem[SM_AS + SM_BS];

    if (blockIdx.x < 125) {
        // ---------- GEMM: 64x128 tile, BK=16, 256 thr, 4x8 micro ----------
        const int tid = threadIdx.x;
        const int tx = tid & 15, ty = tid >> 4;
        const int br = blockIdx.x * 64;
        float* As = smem;            // As[(buf*16+kk)*65 + r]
        float* Bs = smem + SM_AS;    // Bs[(buf*16+kk)*128 + c]

        const int ar = tid >> 2;           // A row within tile
        const int ak = (tid & 3) * 4;      // A k-offset (float4)
        const int bk = tid >> 5;           // B k (and bk+8)
        const int bc = (tid & 31) * 4;     // B col (float4)

        float4 a_r, b_r0, b_r1;
        a_r  = *(const float4*)&x[(size_t)(br + ar) * NFEATD + ak];
        b_r0 = *(const float4*)&W0[(size_t)(bk)     * NHID + bc];
        b_r1 = *(const float4*)&W0[(size_t)(bk + 8) * NHID + bc];
        As[(0 + ak + 0) * 65 + ar] = a_r.x;
        As[(0 + ak + 1) * 65 + ar] = a_r.y;
        As[(0 + ak + 2) * 65 + ar] = a_r.z;
        As[(0 + ak + 3) * 65 + ar] = a_r.w;
        *(float4*)&Bs[(0 + bk)     * 128 + bc] = b_r0;
        *(float4*)&Bs[(0 + bk + 8) * 128 + bc] = b_r1;
        __syncthreads();

        float acc[4][8];
#pragma unroll
        for (int i = 0; i < 4; i++)
#pragma unroll
            for (int j = 0; j < 8; j++) acc[i][j] = 0.f;

        for (int kt = 0; kt < 32; kt++) {
            const int cur = (kt & 1) * 16, nxt = ((kt + 1) & 1) * 16;
            if (kt < 31) {
                const int k0 = (kt + 1) * 16;
                a_r  = *(const float4*)&x[(size_t)(br + ar) * NFEATD + k0 + ak];
                b_r0 = *(const float4*)&W0[(size_t)(k0 + bk)     * NHID + bc];
                b_r1 = *(const float4*)&W0[(size_t)(k0 + bk + 8) * NHID + bc];
            }
#pragma unroll
            for (int kk = 0; kk < 16; kk++) {
                float ra[4], rb[8];
#pragma unroll
                for (int i = 0; i < 4; i++) ra[i] = As[(cur + kk) * 65 + ty * 4 + i];
                *(float4*)&rb[0] = *(float4*)&Bs[(cur + kk) * 128 + tx * 8];
                *(float4*)&rb[4] = *(float4*)&Bs[(cur + kk) * 128 + tx * 8 + 4];
#pragma unroll
                for (int i = 0; i < 4; i++)
#pragma unroll
                    for (int j = 0; j < 8; j++) acc[i][j] += ra[i] * rb[j];
            }
            if (kt < 31) {
                As[(nxt + ak + 0) * 65 + ar] = a_r.x;
                As[(nxt + ak + 1) * 65 + ar] = a_r.y;
                As[(nxt + ak + 2) * 65 + ar] = a_r.z;
                As[(nxt + ak + 3) * 65 + ar] = a_r.w;
                *(float4*)&Bs[(nxt + bk)     * 128 + bc] = b_r0;
                *(float4*)&Bs[(nxt + bk + 8) * 128 + bc] = b_r1;
            }
            __syncthreads();
        }

        const float4 bv0 = *(const float4*)&b0[tx * 8];
        const float4 bv1 = *(const float4*)&b0[tx * 8 + 4];
#pragma unroll
        for (int i = 0; i < 4; i++) {
            const int r = br + ty * 4 + i;
            float4 o0, o1;
            o0.x = fmaxf(acc[i][0] + bv0.x, 0.f);
            o0.y = fmaxf(acc[i][1] + bv0.y, 0.f);
            o0.z = fmaxf(acc[i][2] + bv0.z, 0.f);
            o0.w = fmaxf(acc[i][3] + bv0.w, 0.f);
            o1.x = fmaxf(acc[i][4] + bv1.x, 0.f);
            o1.y = fmaxf(acc[i][5] + bv1.y, 0.f);
            o1.z = fmaxf(acc[i][6] + bv1.z, 0.f);
            o1.w = fmaxf(acc[i][7] + bv1.w, 0.f);
            *(float4*)&g_h[(size_t)r * NHID + tx * 8]       = o0;
            *(float4*)&g_h[(size_t)r * NHID + tx * 8 + 4]   = o1;
            *(float4*)&g_li0[(size_t)r * NHID + tx * 8]     = o0;
            *(float4*)&g_li0[(size_t)r * NHID + tx * 8 + 4] = o1;
        }
    } else {
        // ---------- CSR structure of one adj row (binary values) ----------
        const int i = blockIdx.x - 125;
        const int t = threadIdx.x;
        int* cnt = (int*)smem;
        if (t == 0) *cnt = 0;
        __syncthreads();
        const float4* row4 = (const float4*)(adj + (size_t)i * NN);
        for (int j = t; j < NN / 4; j += 256) {
            float4 v = row4[j];
            if (v.x != 0.f) { int p = atomicAdd(cnt, 1); if (p < CAP) g_cols[i * CAP + p] = 4 * j + 0; }
            if (v.y != 0.f) { int p = atomicAdd(cnt, 1); if (p < CAP) g_cols[i * CAP + p] = 4 * j + 1; }
            if (v.z != 0.f) { int p = atomicAdd(cnt, 1); if (p < CAP) g_cols[i * CAP + p] = 4 * j + 2; }
            if (v.w != 0.f) { int p = atomicAdd(cnt, 1); if (p < CAP) g_cols[i * CAP + p] = 4 * j + 3; }
        }
        __syncthreads();
        if (t == 0) g_nnz[i] = (*cnt < CAP) ? *cnt : CAP;
    }
}

// ============================================================
// Fused: Pseudo = h@W1+b1, label injection (count-based, dup-safe),
// softmax -> g_yhat, Pseudo -> output. 4 rows per block, 64 threads.
// ============================================================
__global__ void __launch_bounds__(64) k_pseudo_sm(
        const float* __restrict__ W1, const float* __restrict__ b1,
        const int* __restrict__ idx, const float* __restrict__ y,
        float* __restrict__ out_pseudo) {
    const int base = blockIdx.x * 4, t = threadIdx.x;
    __shared__ __align__(16) float sh[4 * NHID];
    __shared__ float sred[4 * NCLS];
    __shared__ float smx[4], ssum[4];
    __shared__ int scnt[4];
    if (t < 4) scnt[t] = 0;
    const float4* hp = (const float4*)&g_h[(size_t)base * NHID];
    ((float4*)sh)[t]      = hp[t];
    ((float4*)sh)[t + 64] = hp[t + 64];
    __syncthreads();

    const float b = b1[t];
    float a0 = b, a1 = b, a2 = b, a3 = b;
#pragma unroll 8
    for (int k = 0; k < NHID; k++) {
        const float w = W1[k * NCLS + t];
        a0 += sh[k] * w;
        a1 += sh[NHID + k] * w;
        a2 += sh[2 * NHID + k] * w;
        a3 += sh[3 * NHID + k] * w;
    }
    // count label injections hitting these 4 rows (handles duplicate idx)
    for (int e = t; e < 500; e += 64) {
        const int v = idx[e] - base;
        if ((unsigned)v < 4u) atomicAdd(&scnt[v], 1);
    }
    __syncthreads();
    if (scnt[0]) a0 += 0.1f * scnt[0] * y[(size_t)(base + 0) * NCLS + t];
    if (scnt[1]) a1 += 0.1f * scnt[1] * y[(size_t)(base + 1) * NCLS + t];
    if (scnt[2]) a2 += 0.1f * scnt[2] * y[(size_t)(base + 2) * NCLS + t];
    if (scnt[3]) a3 += 0.1f * scnt[3] * y[(size_t)(base + 3) * NCLS + t];

    out_pseudo[(size_t)(base + 0) * NCLS + t] = a0;
    out_pseudo[(size_t)(base + 1) * NCLS + t] = a1;
    out_pseudo[(size_t)(base + 2) * NCLS + t] = a2;
    out_pseudo[(size_t)(base + 3) * NCLS + t] = a3;
    sred[t] = a0; sred[NCLS + t] = a1; sred[2 * NCLS + t] = a2; sred[3 * NCLS + t] = a3;
    __syncthreads();

    const int warp = t >> 5, lane = t & 31;
#pragma unroll
    for (int rr = 0; rr < 2; rr++) {
        const int r = warp * 2 + rr;
        float m = fmaxf(sred[r * NCLS + lane], sred[r * NCLS + lane + 32]);
#pragma unroll
        for (int o = 16; o; o >>= 1) m = fmaxf(m, __shfl_xor_sync(~0u, m, o));
        float s = expf(sred[r * NCLS + lane] - m) + expf(sred[r * NCLS + lane + 32] - m);
#pragma unroll
        for (int o = 16; o; o >>= 1) s += __shfl_xor_sync(~0u, s, o);
        if (lane == 0) { smx[r] = m; ssum[r] = 1.f / s; }
    }
    __syncthreads();
    g_yhat[(size_t)(base + 0) * NCLS + t] = expf(a0 - smx[0]) * ssum[0];
    g_yhat[(size_t)(base + 1) * NCLS + t] = expf(a1 - smx[1]) * ssum[1];
    g_yhat[(size_t)(base + 2) * NCLS + t] = expf(a2 - smx[2]) * ssum[2];
    g_yhat[(size_t)(base + 3) * NCLS + t] = expf(a3 - smx[3]) * ssum[3];
}

// ============================================================
// One propagation layer (one block of 128 thr per row), fused:
//   w_e = dot(yhat_i, yhat_j); scale = 0.9/max(sum w_e, eps)
//   li_out = L2norm( scale * sum w_e*li_in[j] + 0.1*h0 )
// Edge-accumulate unrolled x4 for MLP; shuffle-based reductions.
// ============================================================
__global__ void __launch_bounds__(128) k_layer(int phase) {
    const int i = blockIdx.x, t = threadIdx.x;
    const float* __restrict__ li_in  = phase ? g_li1 : g_li0;
    float*       __restrict__ li_out = phase ? g_li0 : g_li1;

    __shared__ __align__(16) float syh[NCLS];
    __shared__ int   sj[CAP];
    __shared__ float sw[CAP];
    __shared__ float sred[4];
    __shared__ float sscale;

    const int nnz = g_nnz[i];
    if (t < NCLS) syh[t] = g_yhat[(size_t)i * NCLS + t];
    for (int e = t; e < nnz; e += 128) sj[e] = g_cols[i * CAP + e];
    __syncthreads();

    const int warp = t >> 5, lane = t & 31;
    const float2 ya = ((const float2*)syh)[lane];
    for (int e = warp; e < nnz; e += 4) {
        const float2* yj = (const float2*)(g_yhat + (size_t)sj[e] * NCLS);
        const float2 bv = yj[lane];
        float p = ya.x * bv.x + ya.y * bv.y;
#pragma unroll
        for (int o = 16; o; o >>= 1) p += __shfl_xor_sync(~0u, p, o);
        if (lane == 0) sw[e] = p;
    }
    __syncthreads();
    if (t == 0) {
        float s = 0.f;
        for (int e = 0; e < nnz; e++) s += sw[e];
        sscale = 0.9f / fmaxf(s, 1e-12f);
    }
    __syncthreads();

    float acc = 0.f;
    int e = 0;
    for (; e + 4 <= nnz; e += 4) {
        const float v0 = li_in[(size_t)sj[e]     * NHID + t];
        const float v1 = li_in[(size_t)sj[e + 1] * NHID + t];
        const float v2 = li_in[(size_t)sj[e + 2] * NHID + t];
        const float v3 = li_in[(size_t)sj[e + 3] * NHID + t];
        acc += sw[e] * v0 + sw[e + 1] * v1 + sw[e + 2] * v2 + sw[e + 3] * v3;
    }
    for (; e < nnz; e++) acc += sw[e] * li_in[(size_t)sj[e] * NHID + t];
    acc = acc * sscale + 0.1f * g_h[(size_t)i * NHID + t];

    float sq = acc * acc;
#pragma unroll
    for (int o = 16; o; o >>= 1) sq += __shfl_xor_sync(~0u, sq, o);
    if (lane == 0) sred[warp] = sq;
    __syncthreads();
    const float tot = sred[0] + sred[1] + sred[2] + sred[3];
    li_out[(size_t)i * NHID + t] = acc * (1.f / fmaxf(sqrtf(tot), 1e-12f));
}

// ============================================================
// out = log_softmax(li @ W2 + b2), 4 rows per block, 64 threads
// ============================================================
__global__ void __launch_bounds__(64) k_out(
        const float* __restrict__ W2, const float* __restrict__ b2,
        float* __restrict__ out) {
    const int base = blockIdx.x * 4, t = threadIdx.x;
    __shared__ __align__(16) float sh[4 * NHID];
    __shared__ float sred[4 * NCLS];
    __shared__ float smx[4], ssum[4];
    const float4* lp = (const float4*)&g_li0[(size_t)base * NHID];
    ((float4*)sh)[t]      = lp[t];
    ((float4*)sh)[t + 64] = lp[t + 64];
    __syncthreads();

    const float b = b2[t];
    float a0 = b, a1 = b, a2 = b, a3 = b;
#pragma unroll 8
    for (int k = 0; k < NHID; k++) {
        const float w = W2[k * NCLS + t];
        a0 += sh[k] * w;
        a1 += sh[NHID + k] * w;
        a2 += sh[2 * NHID + k] * w;
        a3 += sh[3 * NHID + k] * w;
    }
    sred[t] = a0; sred[NCLS + t] = a1; sred[2 * NCLS + t] = a2; sred[3 * NCLS + t] = a3;
    __syncthreads();

    const int warp = t >> 5, lane = t & 31;
#pragma unroll
    for (int rr = 0; rr < 2; rr++) {
        const int r = warp * 2 + rr;
        float m = fmaxf(sred[r * NCLS + lane], sred[r * NCLS + lane + 32]);
#pragma unroll
        for (int o = 16; o; o >>= 1) m = fmaxf(m, __shfl_xor_sync(~0u, m, o));
        float s = expf(sred[r * NCLS + lane] - m) + expf(sred[r * NCLS + lane + 32] - m);
#pragma unroll
        for (int o = 16; o; o >>= 1) s += __shfl_xor_sync(~0u, s, o);
        if (lane == 0) { smx[r] = m; ssum[r] = logf(s); }
    }
    __syncthreads();
    out[(size_t)(base + 0) * NCLS + t] = a0 - smx[0] - ssum[0];
    out[(size_t)(base + 1) * NCLS + t] = a1 - smx[1] - ssum[1];
    out[(size_t)(base + 2) * NCLS + t] = a2 - smx[2] - ssum[2];
    out[(size_t)(base + 3) * NCLS + t] = a3 - smx[3] - ssum[3];
}

// ============================================================
extern "C" void kernel_launch(void* const* d_in, const int* in_sizes, int n_in,
                              void* d_out, int out_size) {
    const float* x   = (const float*)d_in[0];
    const float* adj = (const float*)d_in[1];
    const float* y   = (const float*)d_in[2];
    const int*   idx = (const int*)  d_in[3];
    const float* W0  = (const float*)d_in[4];
    const float* b0  = (const float*)d_in[5];
    const float* W1  = (const float*)d_in[6];
    const float* b1  = (const float*)d_in[7];
    const float* W2  = (const float*)d_in[8];
    const float* b2  = (const float*)d_in[9];
    (void)in_sizes; (void)n_in; (void)out_size;

    float* out_logsm  = (float*)d_out;                       // [8000,64]
    float* out_pseudo = (float*)d_out + (size_t)NN * NCLS;   // [8000,64]

    k_main<<<125 + NN, 256>>>(x, W0, b0, adj);     // GEMM tiles + CSR rows, overlapped
    k_pseudo_sm<<<NN / 4, 64>>>(W1, b1, idx, y, out_pseudo);
    k_layer<<<NN, 128>>>(0);                       // li0 -> li1
    k_layer<<<NN, 128>>>(1);                       // li1 -> li0
    k_out<<<NN / 4, 64>>>(W2, b2, out_logsm);      // log_softmax output
}

// round 10
// speedup vs baseline: 1.2615x; 1.2106x over previous
#include <cuda_runtime.h>

#define NN      8000
#define NFEATD  512
#define NHID    128
#define NCLS    64
#define CAP     128
#define NCHUNK  2000   // NN/4 uint4 chunks per adj row

// ---- persistent scratch (no allocs allowed) ----
__device__ float g_h[NN * NHID];        // h = relu(xW0+b0) (== h0)
__device__ float g_li0[NN * NHID];
__device__ float g_li1[NN * NHID];
__device__ float g_yhat[NN * NCLS];
__device__ float g_w[NN * CAP];         // normalized edge weights (incl. 0.9/L1 factor)
__device__ int   g_cols[NN * CAP];
__device__ int   g_nnz[NN];

// ============================================================
// Merged kernel: blocks [0,125) = h-GEMM tiles, [125,8125) = CSR rows.
// CSR scan is issue-lean: 8 uint4 loads up front, single OR-tree + ISETP
// covers 32 elements; slow path (rare) re-examines live registers.
// ============================================================
#define SM_AS   (2 * 16 * 65)
#define SM_BS   (2 * 16 * 128)

__global__ void __launch_bounds__(256) k_main(
        const float* __restrict__ x,  const float* __restrict__ W0,
        const float* __restrict__ b0, const float* __restrict__ adj) {
    __shared__ __align__(16) float smem[SM_AS + SM_BS];

    if (blockIdx.x < 125) {
        // ---------- GEMM: 64x128 tile, BK=16, 256 thr, 4x8 micro ----------
        const int tid = threadIdx.x;
        const int tx = tid & 15, ty = tid >> 4;
        const int br = blockIdx.x * 64;
        float* As = smem;
        float* Bs = smem + SM_AS;

        const int ar = tid >> 2;
        const int ak = (tid & 3) * 4;
        const int bk = tid >> 5;
        const int bc = (tid & 31) * 4;

        float4 a_r, b_r0, b_r1;
        a_r  = *(const float4*)&x[(size_t)(br + ar) * NFEATD + ak];
        b_r0 = *(const float4*)&W0[(size_t)(bk)     * NHID + bc];
        b_r1 = *(const float4*)&W0[(size_t)(bk + 8) * NHID + bc];
        As[(0 + ak + 0) * 65 + ar] = a_r.x;
        As[(0 + ak + 1) * 65 + ar] = a_r.y;
        As[(0 + ak + 2) * 65 + ar] = a_r.z;
        As[(0 + ak + 3) * 65 + ar] = a_r.w;
        *(float4*)&Bs[(0 + bk)     * 128 + bc] = b_r0;
        *(float4*)&Bs[(0 + bk + 8) * 128 + bc] = b_r1;
        __syncthreads();

        float acc[4][8];
#pragma unroll
        for (int i = 0; i < 4; i++)
#pragma unroll
            for (int j = 0; j < 8; j++) acc[i][j] = 0.f;

        for (int kt = 0; kt < 32; kt++) {
            const int cur = (kt & 1) * 16, nxt = ((kt + 1) & 1) * 16;
            if (kt < 31) {
                const int k0 = (kt + 1) * 16;
                a_r  = *(const float4*)&x[(size_t)(br + ar) * NFEATD + k0 + ak];
                b_r0 = *(const float4*)&W0[(size_t)(k0 + bk)     * NHID + bc];
                b_r1 = *(const float4*)&W0[(size_t)(k0 + bk + 8) * NHID + bc];
            }
#pragma unroll
            for (int kk = 0; kk < 16; kk++) {
                float ra[4], rb[8];
#pragma unroll
                for (int i = 0; i < 4; i++) ra[i] = As[(cur + kk) * 65 + ty * 4 + i];
                *(float4*)&rb[0] = *(float4*)&Bs[(cur + kk) * 128 + tx * 8];
                *(float4*)&rb[4] = *(float4*)&Bs[(cur + kk) * 128 + tx * 8 + 4];
#pragma unroll
                for (int i = 0; i < 4; i++)
#pragma unroll
                    for (int j = 0; j < 8; j++) acc[i][j] += ra[i] * rb[j];
            }
            if (kt < 31) {
                As[(nxt + ak + 0) * 65 + ar] = a_r.x;
                As[(nxt + ak + 1) * 65 + ar] = a_r.y;
                As[(nxt + ak + 2) * 65 + ar] = a_r.z;
                As[(nxt + ak + 3) * 65 + ar] = a_r.w;
                *(float4*)&Bs[(nxt + bk)     * 128 + bc] = b_r0;
                *(float4*)&Bs[(nxt + bk + 8) * 128 + bc] = b_r1;
            }
            __syncthreads();
        }

        const float4 bv0 = *(const float4*)&b0[tx * 8];
        const float4 bv1 = *(const float4*)&b0[tx * 8 + 4];
#pragma unroll
        for (int i = 0; i < 4; i++) {
            const int r = br + ty * 4 + i;
            float4 o0, o1;
            o0.x = fmaxf(acc[i][0] + bv0.x, 0.f);
            o0.y = fmaxf(acc[i][1] + bv0.y, 0.f);
            o0.z = fmaxf(acc[i][2] + bv0.z, 0.f);
            o0.w = fmaxf(acc[i][3] + bv0.w, 0.f);
            o1.x = fmaxf(acc[i][4] + bv1.x, 0.f);
            o1.y = fmaxf(acc[i][5] + bv1.y, 0.f);
            o1.z = fmaxf(acc[i][6] + bv1.z, 0.f);
            o1.w = fmaxf(acc[i][7] + bv1.w, 0.f);
            *(float4*)&g_h[(size_t)r * NHID + tx * 8]       = o0;
            *(float4*)&g_h[(size_t)r * NHID + tx * 8 + 4]   = o1;
            *(float4*)&g_li0[(size_t)r * NHID + tx * 8]     = o0;
            *(float4*)&g_li0[(size_t)r * NHID + tx * 8 + 4] = o1;
        }
    } else {
        // ---------- CSR structure of one adj row (issue-lean scan) --------
        const int i = blockIdx.x - 125;
        const int t = threadIdx.x;
        int* cnt = (int*)smem;
        if (t == 0) *cnt = 0;
        __syncthreads();
        const uint4* row4 = (const uint4*)(adj + (size_t)i * NN);

        uint4 c[8];
#pragma unroll
        for (int k = 0; k < 7; k++) c[k] = row4[t + 256 * k];
        {
            const int idx7 = t + 256 * 7;
            if (idx7 < NCHUNK) c[7] = row4[idx7];
            else               c[7] = make_uint4(0u, 0u, 0u, 0u);
        }
        unsigned allor = 0u;
#pragma unroll
        for (int k = 0; k < 8; k++)
            allor |= (c[k].x | c[k].y) | (c[k].z | c[k].w);

        if (allor) {
#pragma unroll
            for (int k = 0; k < 8; k++) {
                const unsigned oc = (c[k].x | c[k].y) | (c[k].z | c[k].w);
                if (oc) {
                    const int base = (t + 256 * k) * 4;
                    if (c[k].x) { int p = atomicAdd(cnt, 1); if (p < CAP) g_cols[i * CAP + p] = base + 0; }
                    if (c[k].y) { int p = atomicAdd(cnt, 1); if (p < CAP) g_cols[i * CAP + p] = base + 1; }
                    if (c[k].z) { int p = atomicAdd(cnt, 1); if (p < CAP) g_cols[i * CAP + p] = base + 2; }
                    if (c[k].w) { int p = atomicAdd(cnt, 1); if (p < CAP) g_cols[i * CAP + p] = base + 3; }
                }
            }
        }
        __syncthreads();
        if (t == 0) g_nnz[i] = (*cnt < CAP) ? *cnt : CAP;
    }
}

// ============================================================
// Fused: Pseudo = h@W1+b1, label injection (count-based, dup-safe),
// softmax -> g_yhat, Pseudo -> output. 4 rows per block, 64 threads.
// ============================================================
__global__ void __launch_bounds__(64) k_pseudo_sm(
        const float* __restrict__ W1, const float* __restrict__ b1,
        const int* __restrict__ idx, const float* __restrict__ y,
        float* __restrict__ out_pseudo) {
    const int base = blockIdx.x * 4, t = threadIdx.x;
    __shared__ __align__(16) float sh[4 * NHID];
    __shared__ float sred[4 * NCLS];
    __shared__ float smx[4], ssum[4];
    __shared__ int scnt[4];
    if (t < 4) scnt[t] = 0;
    const float4* hp = (const float4*)&g_h[(size_t)base * NHID];
    ((float4*)sh)[t]      = hp[t];
    ((float4*)sh)[t + 64] = hp[t + 64];
    __syncthreads();

    const float b = b1[t];
    float a0 = b, a1 = b, a2 = b, a3 = b;
#pragma unroll 8
    for (int k = 0; k < NHID; k++) {
        const float w = W1[k * NCLS + t];
        a0 += sh[k] * w;
        a1 += sh[NHID + k] * w;
        a2 += sh[2 * NHID + k] * w;
        a3 += sh[3 * NHID + k] * w;
    }
    for (int e = t; e < 500; e += 64) {
        const int v = idx[e] - base;
        if ((unsigned)v < 4u) atomicAdd(&scnt[v], 1);
    }
    __syncthreads();
    if (scnt[0]) a0 += 0.1f * scnt[0] * y[(size_t)(base + 0) * NCLS + t];
    if (scnt[1]) a1 += 0.1f * scnt[1] * y[(size_t)(base + 1) * NCLS + t];
    if (scnt[2]) a2 += 0.1f * scnt[2] * y[(size_t)(base + 2) * NCLS + t];
    if (scnt[3]) a3 += 0.1f * scnt[3] * y[(size_t)(base + 3) * NCLS + t];

    out_pseudo[(size_t)(base + 0) * NCLS + t] = a0;
    out_pseudo[(size_t)(base + 1) * NCLS + t] = a1;
    out_pseudo[(size_t)(base + 2) * NCLS + t] = a2;
    out_pseudo[(size_t)(base + 3) * NCLS + t] = a3;
    sred[t] = a0; sred[NCLS + t] = a1; sred[2 * NCLS + t] = a2; sred[3 * NCLS + t] = a3;
    __syncthreads();

    const int warp = t >> 5, lane = t & 31;
#pragma unroll
    for (int rr = 0; rr < 2; rr++) {
        const int r = warp * 2 + rr;
        float m = fmaxf(sred[r * NCLS + lane], sred[r * NCLS + lane + 32]);
#pragma unroll
        for (int o = 16; o; o >>= 1) m = fmaxf(m, __shfl_xor_sync(~0u, m, o));
        float s = expf(sred[r * NCLS + lane] - m) + expf(sred[r * NCLS + lane + 32] - m);
#pragma unroll
        for (int o = 16; o; o >>= 1) s += __shfl_xor_sync(~0u, s, o);
        if (lane == 0) { smx[r] = m; ssum[r] = 1.f / s; }
    }
    __syncthreads();
    g_yhat[(size_t)(base + 0) * NCLS + t] = expf(a0 - smx[0]) * ssum[0];
    g_yhat[(size_t)(base + 1) * NCLS + t] = expf(a1 - smx[1]) * ssum[1];
    g_yhat[(size_t)(base + 2) * NCLS + t] = expf(a2 - smx[2]) * ssum[2];
    g_yhat[(size_t)(base + 3) * NCLS + t] = expf(a3 - smx[3]) * ssum[3];
}

// ============================================================
// Edge weights (identical across both layers -> computed ONCE):
//   w_e = dot(yhat_i, yhat_j) * 0.9 / max(sum_e dot, eps)
// One block (128 thr) per row; 4-warp cooperative edge dots.
// ============================================================
__global__ void __launch_bounds__(128) k_wts() {
    const int i = blockIdx.x, t = threadIdx.x;
    __shared__ __align__(16) float syh[NCLS];
    __shared__ int   sj[CAP];
    __shared__ float sw[CAP];
    __shared__ float sscale;

    const int nnz = g_nnz[i];
    if (t < NCLS) syh[t] = g_yhat[(size_t)i * NCLS + t];
    for (int e = t; e < nnz; e += 128) sj[e] = g_cols[i * CAP + e];
    __syncthreads();

    const int warp = t >> 5, lane = t & 31;
    const float2 ya = ((const float2*)syh)[lane];
    for (int e = warp; e < nnz; e += 4) {
        const float2 bv = ((const float2*)(g_yhat + (size_t)sj[e] * NCLS))[lane];
        float p = ya.x * bv.x + ya.y * bv.y;
#pragma unroll
        for (int o = 16; o; o >>= 1) p += __shfl_xor_sync(~0u, p, o);
        if (lane == 0) sw[e] = p;
    }
    __syncthreads();
    if (warp == 0) {
        float s = 0.f;
        for (int e = lane; e < nnz; e += 32) s += sw[e];
#pragma unroll
        for (int o = 16; o; o >>= 1) s += __shfl_xor_sync(~0u, s, o);
        if (lane == 0) sscale = 0.9f / fmaxf(s, 1e-12f);
    }
    __syncthreads();
    const float sc = sscale;
    for (int e = t; e < nnz; e += 128) g_w[i * CAP + e] = sw[e] * sc;
}

// ============================================================
// Propagation gather (weights precomputed): warp-per-row, float4 lanes.
//   li_out = L2norm( sum_e w_e*li_in[j_e] + 0.1*h0 )
// 8 rows per 256-thread block.
// ============================================================
__global__ void __launch_bounds__(256) k_gather(int phase) {
    const float* __restrict__ li_in  = phase ? g_li1 : g_li0;
    float*       __restrict__ li_out = phase ? g_li0 : g_li1;
    const int i    = blockIdx.x * 8 + (threadIdx.x >> 5);
    const int lane = threadIdx.x & 31;
    const int nnz  = g_nnz[i];
    const int*   __restrict__ cols = &g_cols[i * CAP];
    const float* __restrict__ wts  = &g_w[i * CAP];

    const float4 h4 = ((const float4*)(g_h + (size_t)i * NHID))[lane];
    float4 a0 = make_float4(0.1f * h4.x, 0.1f * h4.y, 0.1f * h4.z, 0.1f * h4.w);
    float4 a1 = make_float4(0.f, 0.f, 0.f, 0.f);

    int e = 0;
    for (; e + 2 <= nnz; e += 2) {
        const int   j0 = cols[e],     j1 = cols[e + 1];
        const float w0 = wts[e],      w1 = wts[e + 1];
        const float4 v0 = ((const float4*)(li_in + (size_t)j0 * NHID))[lane];
        const float4 v1 = ((const float4*)(li_in + (size_t)j1 * NHID))[lane];
        a0.x += w0 * v0.x; a0.y += w0 * v0.y; a0.z += w0 * v0.z; a0.w += w0 * v0.w;
        a1.x += w1 * v1.x; a1.y += w1 * v1.y; a1.z += w1 * v1.z; a1.w += w1 * v1.w;
    }
    if (e < nnz) {
        const float w0 = wts[e];
        const float4 v0 = ((const float4*)(li_in + (size_t)cols[e] * NHID))[lane];
        a0.x += w0 * v0.x; a0.y += w0 * v0.y; a0.z += w0 * v0.z; a0.w += w0 * v0.w;
    }
    float4 acc = make_float4(a0.x + a1.x, a0.y + a1.y, a0.z + a1.z, a0.w + a1.w);

    float sq = acc.x * acc.x + acc.y * acc.y + acc.z * acc.z + acc.w * acc.w;
#pragma unroll
    for (int o = 16; o; o >>= 1) sq += __shfl_xor_sync(~0u, sq, o);
    const float inv = 1.f / fmaxf(sqrtf(sq), 1e-12f);
    acc.x *= inv; acc.y *= inv; acc.z *= inv; acc.w *= inv;
    ((float4*)(li_out + (size_t)i * NHID))[lane] = acc;
}

// ============================================================
// out = log_softmax(li @ W2 + b2), 4 rows per block, 64 threads
// ============================================================
__global__ void __launch_bounds__(64) k_out(
        const float* __restrict__ W2, const float* __restrict__ b2,
        float* __restrict__ out) {
    const int base = blockIdx.x * 4, t = threadIdx.x;
    __shared__ __align__(16) float sh[4 * NHID];
    __shared__ float sred[4 * NCLS];
    __shared__ float smx[4], ssum[4];
    const float4* lp = (const float4*)&g_li0[(size_t)base * NHID];
    ((float4*)sh)[t]      = lp[t];
    ((float4*)sh)[t + 64] = lp[t + 64];
    __syncthreads();

    const float b = b2[t];
    float a0 = b, a1 = b, a2 = b, a3 = b;
#pragma unroll 8
    for (int k = 0; k < NHID; k++) {
        const float w = W2[k * NCLS + t];
        a0 += sh[k] * w;
        a1 += sh[NHID + k] * w;
        a2 += sh[2 * NHID + k] * w;
        a3 += sh[3 * NHID + k] * w;
    }
    sred[t] = a0; sred[NCLS + t] = a1; sred[2 * NCLS + t] = a2; sred[3 * NCLS + t] = a3;
    __syncthreads();

    const int warp = t >> 5, lane = t & 31;
#pragma unroll
    for (int rr = 0; rr < 2; rr++) {
        const int r = warp * 2 + rr;
        float m = fmaxf(sred[r * NCLS + lane], sred[r * NCLS + lane + 32]);
#pragma unroll
        for (int o = 16; o; o >>= 1) m = fmaxf(m, __shfl_xor_sync(~0u, m, o));
        float s = expf(sred[r * NCLS + lane] - m) + expf(sred[r * NCLS + lane + 32] - m);
#pragma unroll
        for (int o = 16; o; o >>= 1) s += __shfl_xor_sync(~0u, s, o);
        if (lane == 0) { smx[r] = m; ssum[r] = logf(s); }
    }
    __syncthreads();
    out[(size_t)(base + 0) * NCLS + t] = a0 - smx[0] - ssum[0];
    out[(size_t)(base + 1) * NCLS + t] = a1 - smx[1] - ssum[1];
    out[(size_t)(base + 2) * NCLS + t] = a2 - smx[2] - ssum[2];
    out[(size_t)(base + 3) * NCLS + t] = a3 - smx[3] - ssum[3];
}

// ============================================================
extern "C" void kernel_launch(void* const* d_in, const int* in_sizes, int n_in,
                              void* d_out, int out_size) {
    const float* x   = (const float*)d_in[0];
    const float* adj = (const float*)d_in[1];
    const float* y   = (const float*)d_in[2];
    const int*   idx = (const int*)  d_in[3];
    const float* W0  = (const float*)d_in[4];
    const float* b0  = (const float*)d_in[5];
    const float* W1  = (const float*)d_in[6];
    const float* b1  = (const float*)d_in[7];
    const float* W2  = (const float*)d_in[8];
    const float* b2  = (const float*)d_in[9];
    (void)in_sizes; (void)n_in; (void)out_size;

    float* out_logsm  = (float*)d_out;                       // [8000,64]
    float* out_pseudo = (float*)d_out + (size_t)NN * NCLS;   // [8000,64]

    k_main<<<125 + NN, 256>>>(x, W0, b0, adj);       // GEMM tiles + CSR rows
    k_pseudo_sm<<<NN / 4, 64>>>(W1, b1, idx, y, out_pseudo);
    k_wts<<<NN, 128>>>();                            // edge weights, once
    k_gather<<<NN / 8, 256>>>(0);                    // li0 -> li1
    k_gather<<<NN / 8, 256>>>(1);                    // li1 -> li0
    k_out<<<NN / 4, 64>>>(W2, b2, out_logsm);        // log_softmax output
}